// round 17
// baseline (speedup 1.0000x reference)
#include <cuda_runtime.h>
#include <cstddef>

#define T_STEPS 300
#define TS_U8   304          // padded stride for u8 spike tensors (16B aligned)
#define THETA 10.0f

// ---------------- scratch ----------------
__device__ float g_bufA[39321600];              // u-chunk / u5 / u6 float scratch
__device__ unsigned char g_bufS[20491008];      // s2[0:9.96M) s4[9.96M:14.9M) x_u8[14.9M:20.5M)
__device__ float g_bufW[32000];                 // packed weights
__device__ float g_bufST[1638400];              // recurrence state (parent + pooled)

#define W1_OFF 0
#define W2_OFF 1280
#define W3_OFF 7424
#define S2_OFF 0
#define S4_OFF 9961472
#define XU8_OFF 14942208

// REF_KERNEL[1..10]: -20*t*exp(1-t), t=1..10 (fp32-rounded from double)
__constant__ float c_refk[10] = {
    -20.0f,
    -14.715177646857693f,
    -8.1201169941967624f,
    -3.9829654694291156f,
    -1.8315638888734179f,
    -0.80855363989025606f,
    -0.34702530473329019f,
    -0.14590111448872260f,
    -0.060383273022452132f,
    -0.024681960817335913f
};

__device__ __forceinline__ float spike_step(float u, float (&buf)[10]) {
    float um = u + buf[0];
    float e = (um >= THETA) ? 1.0f : 0.0f;
#pragma unroll
    for (int j = 0; j < 9; j++) buf[j] = buf[j + 1] + e * c_refk[j];
    buf[9] = e * c_refk[9];
    return e;   // TS = 1 -> amplitude 1
}

// packed 2x fp32 fma (Blackwell FFMA2). Bit-identical to two fmaf's.
__device__ __forceinline__ void ffma2(float2& c, float2 a, float2 b) {
    unsigned long long au = *reinterpret_cast<unsigned long long*>(&a);
    unsigned long long bu = *reinterpret_cast<unsigned long long*>(&b);
    unsigned long long cu = *reinterpret_cast<unsigned long long*>(&c);
    asm("fma.rn.f32x2 %0, %1, %2, %0;" : "+l"(cu) : "l"(au), "l"(bu));
    *reinterpret_cast<unsigned long long*>(&c) = cu;
}

__device__ __forceinline__ void ffma4(float4& c, const float4& a, float w) {
    float2 wv = make_float2(w, w);
    float2 clo = make_float2(c.x, c.y), chi = make_float2(c.z, c.w);
    ffma2(clo, make_float2(a.x, a.y), wv);
    ffma2(chi, make_float2(a.z, a.w), wv);
    c.x = clo.x; c.y = clo.y; c.z = chi.x; c.w = chi.y;
}

__device__ __forceinline__ float f4_get(const float4& v, int i) {
    return i == 0 ? v.x : i == 1 ? v.y : i == 2 ? v.z : v.w;
}

__device__ __forceinline__ float4 load_quad(const float* p) {
    return *(const float4*)p;
}
__device__ __forceinline__ float4 load_quad(const unsigned char* p) {
    uchar4 c = *(const uchar4*)p;
    return make_float4((float)c.x, (float)c.y, (float)c.z, (float)c.w);
}

// ---------------- weight packing: [co][ci][ky][WROW] 16B-aligned rows ---------
__global__ void pack_weights_kernel(const float* __restrict__ w1,
                                    const float* __restrict__ w2,
                                    const float* __restrict__ w3,
                                    float* __restrict__ wp)
{
    int i = blockIdx.x * blockDim.x + threadIdx.x;
    if (i < 1280) {                       // w1: [16][2][5][8]
        int kx = i % 8; int r = i / 8;
        int ky = r % 5; r /= 5;
        int ci = r % 2; int co = r / 2;
        wp[W1_OFF + i] = (kx < 5) ? w1[((co * 2 + ci) * 5 + ky) * 5 + kx] : 0.0f;
    } else if (i < 1280 + 6144) {         // w2: [32][16][3][4]
        int k = i - 1280;
        int kx = k % 4; int r = k / 4;
        int ky = r % 3; r /= 3;
        int ci = r % 16; int co = r / 16;
        wp[W2_OFF + k] = (kx < 3) ? w2[((co * 16 + ci) * 3 + ky) * 3 + kx] : 0.0f;
    } else if (i < 1280 + 6144 + 24576) { // w3: [64][32][3][4]
        int k = i - 1280 - 6144;
        int kx = k % 4; int r = k / 4;
        int ky = r % 3; r /= 3;
        int ci = r % 32; int co = r / 32;
        wp[W3_OFF + k] = (kx < 3) ? w3[((co * 32 + ci) * 3 + ky) * 3 + kx] : 0.0f;
    }
}

// ---------------- input fp32 {0,1} -> u8 (exact) ----------------
__global__ void x_to_u8_kernel(const float* __restrict__ x, unsigned char* __restrict__ y)
{
    int i = blockIdx.x * blockDim.x + threadIdx.x;
    if (i < 1387200) {
        float4 v = ((const float4*)x)[i];
        ((uchar4*)y)[i] = make_uchar4((unsigned char)v.x, (unsigned char)v.y,
                                      (unsigned char)v.z, (unsigned char)v.w);
    }
}

// ---------------- conv: float4 over time, XR=4, COB=4, YB rows, T-chunked -----
// Processes input timesteps [t_base, t_base+ch_len); writes u chunk with
// chunk-local stride ch_len. Same FMA order as monolithic -> bit-exact.
template <typename IT, int IN_TS,
          int Ci, int Hi, int Wi, int Co, int Ho, int Wo, int K, int PAD, int TPQ,
          int WROW, int YB>
__global__ void __launch_bounds__(TPQ * 32, 2)
conv_kernel(const IT* __restrict__ in, const float* __restrict__ w,
            float* __restrict__ out, int t_base, int ch_len, int ntc)
{
    constexpr int WT  = Wo + K - 1;
    constexpr int RT  = K + YB - 1;
    constexpr int XR  = 4;
    constexpr int COB = 4;
    constexpr int XG  = Wo / XR;
    constexpr int CG  = Co / COB;
    static_assert(XG * CG == 32, "one item per ty");
    constexpr int TCH = 4 * TPQ;
    constexpr int NTH = TPQ * 32;

    extern __shared__ char smraw[];
    float4* sm4 = (float4*)smraw;

    int bid = blockIdx.x;
    int tc  = bid % ntc;
    int yg  = (bid / ntc) % (Ho / YB);
    int b   = bid / (ntc * (Ho / YB));
    int yo0 = yg * YB;
    int t0  = tc * TCH;                 // chunk-local

    int tid = threadIdx.y * TPQ + threadIdx.x;

    constexpr int TILE4 = Ci * RT * WT * TPQ;
    for (int flat = tid; flat < TILE4; flat += NTH) {
        int tt = flat % TPQ;
        int r  = flat / TPQ;
        int xw = r % WT; r /= WT;
        int rr = r % RT;
        int ci = r / RT;
        int xi = xw - PAD;
        int yi = yo0 - PAD + rr;
        int tg = t_base + t0 + 4 * tt;  // global input t
        float4 v = make_float4(0.0f, 0.0f, 0.0f, 0.0f);
        if (xi >= 0 && xi < Wi && yi >= 0 && yi < Hi && tg < T_STEPS)
            v = load_quad(&in[((((size_t)b * Ci + ci) * Hi + yi) * Wi + xi) * IN_TS + tg]);
        sm4[flat] = v;
    }
    __syncthreads();

    int tx = threadIdx.x;
    int tl = t0 + 4 * tx;               // chunk-local output t
    int item = threadIdx.y;
    int co0 = (item / XG) * COB;
    int xo0 = (item % XG) * XR;

#pragma unroll
    for (int yb = 0; yb < YB; yb++) {
        int yo = yo0 + yb;

        float4 acc[COB][XR];
#pragma unroll
        for (int j = 0; j < COB; j++)
#pragma unroll
            for (int r = 0; r < XR; r++) acc[j][r] = make_float4(0.0f, 0.0f, 0.0f, 0.0f);

        for (int ci = 0; ci < Ci; ci++) {
#pragma unroll
            for (int ky = 0; ky < K; ky++) {
                float4 v[K + XR - 1];
                const float4* sp = &sm4[((ci * RT + yb + ky) * WT + xo0) * TPQ + tx];
#pragma unroll
                for (int j = 0; j < K + XR - 1; j++) v[j] = sp[j * TPQ];
                float4 wq[COB][WROW / 4];
#pragma unroll
                for (int j = 0; j < COB; j++)
#pragma unroll
                    for (int p = 0; p < WROW / 4; p++)
                        wq[j][p] = *(const float4*)&w[(((size_t)(co0 + j) * Ci + ci) * K + ky) * WROW + 4 * p];
#pragma unroll
                for (int kx = 0; kx < K; kx++)
#pragma unroll
                    for (int j = 0; j < COB; j++)
#pragma unroll
                        for (int r = 0; r < XR; r++)
                            ffma4(acc[j][r], v[kx + r], f4_get(wq[j][kx >> 2], kx & 3));
            }
        }

        if (tl < ch_len) {
#pragma unroll
            for (int j = 0; j < COB; j++)
#pragma unroll
                for (int r = 0; r < XR; r++)
                    *(float4*)&out[(size_t)((((b * Co + co0 + j) * Ho + yo) * Wo + xo0 + r)) * ch_len + tl]
                        = acc[j][r];
        }
    }
}

// ---------------- fused spike+pool+spike, T-chunked with state save/restore ---
__device__ __forceinline__ unsigned int pool_quad(float4 uv, float (&bufp)[10],
                                                  float (&bp)[10]) {
    float p0 = spike_step(uv.x, bufp);
    float p1 = spike_step(uv.y, bufp);
    float p2 = spike_step(uv.z, bufp);
    float p3 = spike_step(uv.w, bufp);
    p0 += __shfl_xor_sync(0xffffffffu, p0, 1); p0 += __shfl_xor_sync(0xffffffffu, p0, 2);
    p1 += __shfl_xor_sync(0xffffffffu, p1, 1); p1 += __shfl_xor_sync(0xffffffffu, p1, 2);
    p2 += __shfl_xor_sync(0xffffffffu, p2, 1); p2 += __shfl_xor_sync(0xffffffffu, p2, 2);
    p3 += __shfl_xor_sync(0xffffffffu, p3, 1); p3 += __shfl_xor_sync(0xffffffffu, p3, 2);
    unsigned int e0 = (unsigned int)spike_step(11.0f * p0, bp);
    unsigned int e1 = (unsigned int)spike_step(11.0f * p1, bp);
    unsigned int e2 = (unsigned int)spike_step(11.0f * p2, bp);
    unsigned int e3 = (unsigned int)spike_step(11.0f * p3, bp);
    return e0 | (e1 << 8) | (e2 << 16) | (e3 << 24);
}

__global__ void __launch_bounds__(128)
spikepool_chunk_kernel(const float* __restrict__ u, unsigned char* __restrict__ s,
                       float* __restrict__ stP, float* __restrict__ stQ,
                       int C, int Ho, int Wo, int nq, int qbase, int first, int last)
{
    int idx = blockIdx.x * 128 + threadIdx.x;
    int sub = idx & 3;
    int n   = idx >> 2;
    int total = 8 * C * Ho * Wo;
    if (n >= total) return;
    int x  = n % Wo;
    int y  = (n / Wo) % Ho;
    int cb = n / (Wo * Ho);

    int dy = sub >> 1, dx = sub & 1;
    size_t row = (((size_t)cb * (2 * Ho) + 2 * y + dy) * (2 * Wo) + 2 * x + dx);
    const float4* up = (const float4*)u + row * nq;
    unsigned char* sp = s + (size_t)n * TS_U8;

    float bufp[10], bp[10];
    if (first) {
#pragma unroll
        for (int j = 0; j < 10; j++) { bufp[j] = 0.0f; bp[j] = 0.0f; }
    } else {
        const float* ps = stP + ((size_t)n * 4 + sub) * 10;
        const float* qs = stQ + (size_t)n * 10;
#pragma unroll
        for (int j = 0; j < 10; j++) { bufp[j] = ps[j]; bp[j] = qs[j]; }
    }

    int ng4 = nq >> 2, rem = nq & 3;
    uint4* sp4 = (uint4*)sp + (qbase >> 2);   // qbase is a multiple of 4
    for (int g = 0; g < ng4; g++) {
        float4 v[4];
#pragma unroll
        for (int i = 0; i < 4; i++) v[i] = up[g * 4 + i];
        unsigned int wd[4];
#pragma unroll
        for (int i = 0; i < 4; i++) wd[i] = pool_quad(v[i], bufp, bp);
        if (sub == 0)
            sp4[g] = make_uint4(wd[0], wd[1], wd[2], wd[3]);
    }
    for (int i = 0; i < rem; i++) {
        float4 v = up[ng4 * 4 + i];
        unsigned int wd = pool_quad(v, bufp, bp);
        if (sub == 0) ((unsigned int*)sp)[qbase + ng4 * 4 + i] = wd;
    }

    if (!last) {
        float* ps = stP + ((size_t)n * 4 + sub) * 10;
#pragma unroll
        for (int j = 0; j < 10; j++) ps[j] = bufp[j];
        if (sub == 0) {
            float* qs = stQ + (size_t)n * 10;
#pragma unroll
            for (int j = 0; j < 10; j++) qs[j] = bp[j];
        }
    }
}

// ---------------- spike with u8 output (layer 5), 64-thr blocks ----------------
__global__ void __launch_bounds__(64)
spike_u8_kernel(const float* __restrict__ u, unsigned char* __restrict__ s, int nNeurons)
{
    int n = blockIdx.x * 64 + threadIdx.x;
    if (n >= nNeurons) return;
    const float4* up = (const float4*)(u + (size_t)n * T_STEPS);
    unsigned char* sp = s + (size_t)n * TS_U8;
    float buf[10];
#pragma unroll
    for (int j = 0; j < 10; j++) buf[j] = 0.0f;

    for (int g = 0; g < 18; g++) {
        float4 v[4];
#pragma unroll
        for (int i = 0; i < 4; i++) v[i] = up[g * 4 + i];
        unsigned int wd[4];
#pragma unroll
        for (int i = 0; i < 4; i++) {
            unsigned int e0 = (unsigned int)spike_step(v[i].x, buf);
            unsigned int e1 = (unsigned int)spike_step(v[i].y, buf);
            unsigned int e2 = (unsigned int)spike_step(v[i].z, buf);
            unsigned int e3 = (unsigned int)spike_step(v[i].w, buf);
            wd[i] = e0 | (e1 << 8) | (e2 << 16) | (e3 << 24);
        }
        ((uint4*)sp)[g] = make_uint4(wd[0], wd[1], wd[2], wd[3]);
    }
    {
        float4 v[3];
#pragma unroll
        for (int i = 0; i < 3; i++) v[i] = up[72 + i];
#pragma unroll
        for (int i = 0; i < 3; i++) {
            unsigned int e0 = (unsigned int)spike_step(v[i].x, buf);
            unsigned int e1 = (unsigned int)spike_step(v[i].y, buf);
            unsigned int e2 = (unsigned int)spike_step(v[i].z, buf);
            unsigned int e3 = (unsigned int)spike_step(v[i].w, buf);
            ((unsigned int*)sp)[72 + i] = e0 | (e1 << 8) | (e2 << 16) | (e3 << 24);
        }
    }
}

// ---------------- FC: block = (b, t-quad); s5 chunk staged in smem ------------
__global__ void __launch_bounds__(320, 3)
fc_kernel(const unsigned char* __restrict__ s5, const float* __restrict__ wfc,
          float* __restrict__ u_out)
{
    constexpr int NQ = T_STEPS / 4;
    int q = blockIdx.x % NQ;
    int b = blockIdx.x / NQ;
    int t0 = q * 4;

    extern __shared__ float4 s_sm[];
    int tid = threadIdx.y * 32 + threadIdx.x;

    const unsigned char* sb = s5 + (size_t)b * 4096 * TS_U8 + t0;
    for (int c = tid; c < 4096; c += 320) {
        uchar4 cc = *(const uchar4*)&sb[(size_t)c * TS_U8];
        s_sm[c] = make_float4((float)cc.x, (float)cc.y, (float)cc.z, (float)cc.w);
    }
    __syncthreads();

    int o    = threadIdx.y;
    int lane = threadIdx.x;
    const float* wo = wfc + o * 4096;

    float4 acc = make_float4(0.0f, 0.0f, 0.0f, 0.0f);
    for (int c = lane; c < 4096; c += 32) {
        float4 v = s_sm[c];
        float wgt = __ldg(&wo[c]);
        acc.x = fmaf(v.x, wgt, acc.x);
        acc.y = fmaf(v.y, wgt, acc.y);
        acc.z = fmaf(v.z, wgt, acc.z);
        acc.w = fmaf(v.w, wgt, acc.w);
    }
#pragma unroll
    for (int d = 16; d >= 1; d >>= 1) {
        acc.x += __shfl_xor_sync(0xffffffffu, acc.x, d);
        acc.y += __shfl_xor_sync(0xffffffffu, acc.y, d);
        acc.z += __shfl_xor_sync(0xffffffffu, acc.z, d);
        acc.w += __shfl_xor_sync(0xffffffffu, acc.w, d);
    }
    if (lane == 0)
        *(float4*)&u_out[(size_t)(b * 10 + o) * T_STEPS + t0] = acc;
}

// ---------------- final spike on 80 neurons ----------------
__global__ void spike_final_kernel(const float* __restrict__ u, float* __restrict__ out)
{
    int n = threadIdx.x;
    if (n >= 80) return;
    const float4* up = (const float4*)(u + (size_t)n * T_STEPS);
    float4*       sp = (float4*)(out + (size_t)n * T_STEPS);
    float buf[10];
#pragma unroll
    for (int j = 0; j < 10; j++) buf[j] = 0.0f;
    for (int q = 0; q < T_STEPS / 4; q++) {
        float4 uv = up[q];
        float4 ev;
        ev.x = spike_step(uv.x, buf);
        ev.y = spike_step(uv.y, buf);
        ev.z = spike_step(uv.z, buf);
        ev.w = spike_step(uv.w, buf);
        sp[q] = ev;
    }
}

// ---------------- launcher ----------------
extern "C" void kernel_launch(void* const* d_in, const int* in_sizes, int n_in,
                              void* d_out, int out_size)
{
    const float* x   = (const float*)d_in[0];
    const float* w1  = (const float*)d_in[1];
    const float* w2  = (const float*)d_in[2];
    const float* w3  = (const float*)d_in[3];
    const float* wfc = (const float*)d_in[4];
    float* out = (float*)d_out;

    float *A = nullptr, *W = nullptr, *ST = nullptr;
    unsigned char *S = nullptr;
    cudaGetSymbolAddress((void**)&A, g_bufA);
    cudaGetSymbolAddress((void**)&S, g_bufS);
    cudaGetSymbolAddress((void**)&W, g_bufW);
    cudaGetSymbolAddress((void**)&ST, g_bufST);

    unsigned char* s2  = S + S2_OFF;
    unsigned char* s4  = S + S4_OFF;
    unsigned char* xu8 = S + XU8_OFF;
    // state: parent buffers then pooled buffers (layer1 max: 32768 neurons)
    float* stP = ST;
    float* stQ = ST + 32768 * 4 * 10;

    constexpr int SM1 = 2  * 6 * 36 * 8 * 16;   //  55296  (K=5, YB=2, TPQ=8)
    constexpr int SM2 = 16 * 3 * 18 * 8 * 16;   // 110592  (K=3, YB=1, TPQ=8)
    constexpr int SM3 = 32 * 3 * 10 * 6 * 16;   //  92160  (K=3, YB=1, TPQ=6)
    constexpr int SMF = 4096 * 16;              //  65536

    cudaFuncSetAttribute((const void*)conv_kernel<unsigned char,T_STEPS,2,34,34,16,32,32,5,1,8,8,2>,
                         cudaFuncAttributeMaxDynamicSharedMemorySize, SM1);
    cudaFuncSetAttribute((const void*)conv_kernel<unsigned char,TS_U8,16,16,16,32,16,16,3,1,8,4,1>,
                         cudaFuncAttributeMaxDynamicSharedMemorySize, SM2);
    cudaFuncSetAttribute((const void*)conv_kernel<unsigned char,TS_U8,32,8,8,64,8,8,3,1,6,4,1>,
                         cudaFuncAttributeMaxDynamicSharedMemorySize, SM3);
    cudaFuncSetAttribute((const void*)fc_kernel,
                         cudaFuncAttributeMaxDynamicSharedMemorySize, SMF);

    // prep
    pack_weights_kernel<<<(32000 + 255) / 256, 256>>>(w1, w2, w3, W);
    x_to_u8_kernel<<<(1387200 + 255) / 256, 256>>>(x, xu8);

    // T-chunks: 96 + 96 + 108 (conv tile counts 3/3/4); qbase multiples of 4
    const int cbase[3] = {0, 96, 192};
    const int clen [3] = {96, 96, 108};
    const int cntc [3] = {3, 3, 4};

    // ---- layer 1: conv1-chunk -> spikepool-chunk (u1 chunk stays in L2) ----
    for (int c = 0; c < 3; c++) {
        conv_kernel<unsigned char,T_STEPS,2,34,34,16,32,32,5,1,8,8,2>
            <<<8 * 16 * cntc[c], dim3(8, 32), SM1>>>(xu8, W + W1_OFF, A,
                                                     cbase[c], clen[c], cntc[c]);
        spikepool_chunk_kernel<<<(32768 * 4) / 128, 128>>>(
            A, s2, stP, stQ, 16, 16, 16, clen[c] / 4, cbase[c] / 4,
            c == 0, c == 2);
    }

    // ---- layer 2: conv2-chunk -> spikepool-chunk ----
    for (int c = 0; c < 3; c++) {
        conv_kernel<unsigned char,TS_U8,16,16,16,32,16,16,3,1,8,4,1>
            <<<8 * 16 * cntc[c], dim3(8, 32), SM2>>>(s2, W + W2_OFF, A,
                                                     cbase[c], clen[c], cntc[c]);
        spikepool_chunk_kernel<<<(16384 * 4) / 128, 128>>>(
            A, s4, stP, stQ, 32, 8, 8, clen[c] / 4, cbase[c] / 4,
            c == 0, c == 2);
    }

    // ---- layer 3 (u5 = 39MB fits L2; monolithic) ----
    conv_kernel<unsigned char,TS_U8,32,8,8,64,8,8,3,1,6,4,1>
        <<<8 * 8 * 13, dim3(6, 32), SM3>>>(s4, W + W3_OFF, A, 0, T_STEPS, 13);
    // spike5: A -> s5 (reuse s2 region; s2 dead after conv2 chunks)
    spike_u8_kernel<<<32768 / 64, 64>>>(A, s2, 32768);
    // FC: s5 -> u6 (A)
    fc_kernel<<<8 * 75, dim3(32, 10), SMF>>>(s2, wfc, A);
    // final spike: u6 -> out
    spike_final_kernel<<<1, 96>>>(A, out);
}